// round 6
// baseline (speedup 1.0000x reference)
#include <cuda_runtime.h>
#include <cuda_bf16.h>
#include <cuda_fp8.h>
#include <cstdint>

// ---------------------------------------------------------------------------
// Problem constants
// ---------------------------------------------------------------------------
#define DIN   4096
#define DOUT  4096
#define MTOT  8192
#define NCHUNK 128          // 64 bf16 chunks (k=64 each) + 64 fp8 chunks (k=128 each)
#define BM    128
#define BN    128
#define NSTAGE 3
#define STAGE_BYTES 32768   // A 16KB + B 16KB (128 rows x 128B each)
#define SMEM_TOTAL (NSTAGE * STAGE_BYTES)   // 96 KB
static __device__ __constant__ float kScaling = 2.0f;   // 32 / rank(16)

// fp8 scale exponents (products are unit-scale -> shared accumulator)
#define S2A 64.0f     // Xlo * 2^6   (e4m3)
#define S2B (1.0f/64.0f)  // Whi * 2^-6  (e5m2)
#define S3A 0.125f    // Xhi * 2^-3  (e4m3)
#define S3B 8.0f      // Wlo * 2^3   (e5m2)

// ---------------------------------------------------------------------------
// Device-global scratch
// ---------------------------------------------------------------------------
__device__ __nv_bfloat16 g_Xhi [(size_t)MTOT * DIN];  // bf16(x)
__device__ uint8_t       g_Xlo8[(size_t)MTOT * DIN];  // e4m3((x-Xhi)*2^6)
__device__ uint8_t       g_Xhi8[(size_t)MTOT * DIN];  // e4m3(Xhi*2^-3)
__device__ __nv_bfloat16 g_Whi [(size_t)DOUT * DIN];  // bf16(W_eff)
__device__ uint8_t       g_Whi8[(size_t)DOUT * DIN];  // e5m2(Whi*2^-6)
__device__ uint8_t       g_Wlo8[(size_t)DOUT * DIN];  // e5m2((W_eff-Whi)*2^3)
__device__ int g_flags[2];
__device__ int g_mode;

// ---------------------------------------------------------------------------
// Helpers (baseline PTX only)
// ---------------------------------------------------------------------------
__device__ __forceinline__ uint32_t smem_u32(const void* p) {
    uint32_t a;
    asm("{ .reg .u64 t; cvta.to.shared.u64 t, %1; cvt.u32.u64 %0, t; }" : "=r"(a) : "l"(p));
    return a;
}
__device__ __forceinline__ void cp_async16(uint32_t dst, const void* src) {
    asm volatile("cp.async.cg.shared.global [%0], [%1], 16;"
                 :: "r"(dst), "l"(__cvta_generic_to_global(src)));
}
#define CP_COMMIT() asm volatile("cp.async.commit_group;" ::: "memory")
#define CP_WAIT(n)  asm volatile("cp.async.wait_group %0;" :: "n"(n) : "memory")

__device__ __forceinline__ uint32_t swz(uint32_t o) { return o ^ ((o >> 3) & 0x70); }

__device__ __forceinline__ void ldsm_x4(uint32_t* r, uint32_t addr) {
    asm volatile("ldmatrix.sync.aligned.m8n8.x4.shared.b16 {%0,%1,%2,%3}, [%4];"
                 : "=r"(r[0]), "=r"(r[1]), "=r"(r[2]), "=r"(r[3]) : "r"(addr));
}
__device__ __forceinline__ void mma_bf16(float* c, const uint32_t* a,
                                         uint32_t b0, uint32_t b1) {
    asm volatile(
        "mma.sync.aligned.m16n8k16.row.col.f32.bf16.bf16.f32 "
        "{%0,%1,%2,%3}, {%4,%5,%6,%7}, {%8,%9}, {%0,%1,%2,%3};"
        : "+f"(c[0]), "+f"(c[1]), "+f"(c[2]), "+f"(c[3])
        : "r"(a[0]), "r"(a[1]), "r"(a[2]), "r"(a[3]), "r"(b0), "r"(b1));
}
// fp8 mma: A = e4m3 (row), B = e5m2 (col), f32 acc. Fragment layout is the
// bf16-k16 layout with each b16 element = 2 consecutive fp8 along k.
__device__ __forceinline__ void mma_fp8(float* c, const uint32_t* a,
                                        uint32_t b0, uint32_t b1) {
    asm volatile(
        "mma.sync.aligned.m16n8k32.row.col.f32.e4m3.e5m2.f32 "
        "{%0,%1,%2,%3}, {%4,%5,%6,%7}, {%8,%9}, {%0,%1,%2,%3};"
        : "+f"(c[0]), "+f"(c[1]), "+f"(c[2]), "+f"(c[3])
        : "r"(a[0]), "r"(a[1]), "r"(a[2]), "r"(a[3]), "r"(b0), "r"(b1));
}

__device__ __forceinline__ uint8_t to_e4m3(float v) {
    return (uint8_t)__nv_cvt_float_to_fp8(v, __NV_SATFINITE, __NV_E4M3);
}
__device__ __forceinline__ uint8_t to_e5m2(float v) {
    return (uint8_t)__nv_cvt_float_to_fp8(v, __NV_SATFINITE, __NV_E5M2);
}

// ---------------------------------------------------------------------------
// Mask dtype detection (first 16MB scan = safe lower bound for all dtypes)
// ---------------------------------------------------------------------------
__global__ void reset_flags_kernel() { g_flags[0] = 0; g_flags[1] = 0; }

__global__ void detect_mask_kernel(const unsigned int* __restrict__ w, int nwords) {
    int notF = 0, notI = 0;
    int stride = gridDim.x * blockDim.x;
    for (int i = blockIdx.x * blockDim.x + threadIdx.x; i < nwords; i += stride) {
        unsigned int v = w[i];
        if (v != 0u && v != 0x3F800000u) notF = 1;
        if (v > 1u)                       notI = 1;
    }
    notF = __any_sync(0xFFFFFFFFu, notF);
    notI = __any_sync(0xFFFFFFFFu, notI);
    if ((threadIdx.x & 31) == 0) {
        if (notF) atomicOr(&g_flags[0], 1);
        if (notI) atomicOr(&g_flags[1], 1);
    }
}
__global__ void resolve_mode_kernel() {
    g_mode = (g_flags[0] == 0) ? 0 : ((g_flags[1] == 0) ? 1 : 2);
}

// ---------------------------------------------------------------------------
// Fold W_eff = W + delta*mask + 2*(B@A) → bf16 hi + fp8 derivatives
// ---------------------------------------------------------------------------
__global__ void fold_kernel(const float* __restrict__ W,
                            const float* __restrict__ lora_A,
                            const float* __restrict__ lora_B,
                            const float* __restrict__ delta,
                            const void*  __restrict__ maskp) {
    int o = blockIdx.x;
    __shared__ float br[16];
    if (threadIdx.x < 16) br[threadIdx.x] = lora_B[o * 16 + threadIdx.x] * kScaling;
    __syncthreads();

    const int mode = g_mode;
    const size_t rowoff = (size_t)o * DIN;

    for (int d = threadIdx.x * 4; d < DIN; d += blockDim.x * 4) {
        float4 w4 = *(const float4*)(W + rowoff + d);
        float4 dl = *(const float4*)(delta + rowoff + d);

        float m0, m1, m2, m3;
        if (mode == 0) {
            float4 mf = *(const float4*)((const float*)maskp + rowoff + d);
            m0 = mf.x; m1 = mf.y; m2 = mf.z; m3 = mf.w;
        } else if (mode == 1) {
            int4 mi = *(const int4*)((const int*)maskp + rowoff + d);
            m0 = mi.x ? 1.f : 0.f; m1 = mi.y ? 1.f : 0.f;
            m2 = mi.z ? 1.f : 0.f; m3 = mi.w ? 1.f : 0.f;
        } else {
            uchar4 mu = *(const uchar4*)((const unsigned char*)maskp + rowoff + d);
            m0 = mu.x ? 1.f : 0.f; m1 = mu.y ? 1.f : 0.f;
            m2 = mu.z ? 1.f : 0.f; m3 = mu.w ? 1.f : 0.f;
        }

        float l0 = 0.f, l1 = 0.f, l2 = 0.f, l3 = 0.f;
#pragma unroll
        for (int r = 0; r < 16; r++) {
            float4 a4 = *(const float4*)(lora_A + (size_t)r * DIN + d);
            float s = br[r];
            l0 = fmaf(s, a4.x, l0); l1 = fmaf(s, a4.y, l1);
            l2 = fmaf(s, a4.z, l2); l3 = fmaf(s, a4.w, l3);
        }

        float v[4];
        v[0] = w4.x + dl.x * m0 + l0;
        v[1] = w4.y + dl.y * m1 + l1;
        v[2] = w4.z + dl.z * m2 + l2;
        v[3] = w4.w + dl.w * m3 + l3;

        uint32_t hp = 0, wh8 = 0, wl8 = 0;
        uint32_t hbits[4];
#pragma unroll
        for (int q = 0; q < 4; q++) {
            __nv_bfloat16 h = __float2bfloat16(v[q]);
            float hf = __bfloat162float(h);
            float lo = v[q] - hf;
            hbits[q] = (uint32_t)__bfloat16_as_ushort(h);
            wh8 |= (uint32_t)to_e5m2(hf * S2B) << (q * 8);
            wl8 |= (uint32_t)to_e5m2(lo * S3B) << (q * 8);
        }
        uint2 H = make_uint2(hbits[0] | (hbits[1] << 16), hbits[2] | (hbits[3] << 16));
        *(uint2*)((char*)g_Whi + (rowoff + d) * 2) = H;
        *(uint32_t*)(g_Whi8 + rowoff + d) = wh8;
        *(uint32_t*)(g_Wlo8 + rowoff + d) = wl8;
        (void)hp;
    }
}

// ---------------------------------------------------------------------------
// X → bf16 hi + fp8 derivatives
// ---------------------------------------------------------------------------
__global__ void convert_x_kernel(const float* __restrict__ x) {
    size_t base = ((size_t)blockIdx.x * blockDim.x + threadIdx.x) * 4;
    float4 vv = *(const float4*)(x + base);
    float v[4] = {vv.x, vv.y, vv.z, vv.w};
    uint32_t hbits[4], xl8 = 0, xh8 = 0;
#pragma unroll
    for (int q = 0; q < 4; q++) {
        __nv_bfloat16 h = __float2bfloat16(v[q]);
        float hf = __bfloat162float(h);
        float lo = v[q] - hf;
        hbits[q] = (uint32_t)__bfloat16_as_ushort(h);
        xl8 |= (uint32_t)to_e4m3(lo * S2A) << (q * 8);
        xh8 |= (uint32_t)to_e4m3(hf * S3A) << (q * 8);
    }
    uint2 H = make_uint2(hbits[0] | (hbits[1] << 16), hbits[2] | (hbits[3] << 16));
    *(uint2*)((char*)g_Xhi + base * 2) = H;
    *(uint32_t*)(g_Xlo8 + base) = xl8;
    *(uint32_t*)(g_Xhi8 + base) = xh8;
}

// ---------------------------------------------------------------------------
// Hybrid bf16+fp8 HMMA GEMM (R3 tile config: 128x128, 8 warps 4m x 2n,
// warp tile 32x64, 3-stage cp.async, 2 CTA/SM).
// chunks 0..63  : bf16  Xhi·Whi      (64 k-elems / chunk)
// chunks 64..95 : fp8   Xlo8·Whi8    (128 k-elems / chunk, unit product scale)
// chunks 96..127: fp8   Xhi8·Wlo8    (128 k-elems / chunk, unit product scale)
// ---------------------------------------------------------------------------
__global__ __launch_bounds__(256, 2)
void gemm_kernel(const float* __restrict__ bias, float* __restrict__ out) {
    extern __shared__ __align__(1024) char smem[];
    const uint32_t sbase = smem_u32(smem);
    const int tid = threadIdx.x;
    const int lane = tid & 31;
    const int wid = tid >> 5;
    const int warpM = wid >> 1;           // 0..3
    const int warpN = wid & 1;            // 0..1
    const int bm = blockIdx.x * BM;       // m fastest → W stays L2-resident
    const int bn = blockIdx.y * BN;

    // loader mapping: 4 A-slots + 4 B-slots of 16B per thread per chunk
    int rowL[4];  uint32_t dstL[4];  int colByte[4];
#pragma unroll
    for (int i = 0; i < 4; i++) {
        int slot = tid + 256 * i;         // 0..1023
        rowL[i] = slot >> 3;              // 0..127
        colByte[i] = (slot & 7) * 16;     // byte offset within 128B row
        dstL[i] = swz((uint32_t)(rowL[i] * 128 + colByte[i]));
    }

    // ldmatrix per-lane swizzled offsets (swizzle applied to full offset)
    const int arow  = (lane & 7) + ((lane >> 3) & 1) * 8;
    const int acol  = ((lane >> 4) & 1) * 16;           // byte
    const int brow  = (lane & 7) + ((lane >> 4) & 1) * 8;
    const int bcol  = ((lane >> 3) & 1) * 16;           // byte
    uint32_t relA[2][4], relB[4][4];
#pragma unroll
    for (int mt = 0; mt < 2; mt++)
#pragma unroll
        for (int ks = 0; ks < 4; ks++)
            relA[mt][ks] = swz((uint32_t)((warpM * 32 + mt * 16 + arow) * 128 + ks * 32 + acol));
#pragma unroll
    for (int p = 0; p < 4; p++)
#pragma unroll
        for (int ks = 0; ks < 4; ks++)
            relB[p][ks] = swz((uint32_t)((warpN * 64 + p * 16 + brow) * 128 + ks * 32 + bcol));

    float acc[2][8][4];
#pragma unroll
    for (int mt = 0; mt < 2; mt++)
#pragma unroll
        for (int nt = 0; nt < 8; nt++)
#pragma unroll
            for (int q = 0; q < 4; q++) acc[mt][nt][q] = 0.f;

    auto load_chunk = [&](int c, int stage) {
        const char* Ab; const char* Bb; size_t sA; size_t kb;
        if (c < 64) {
            Ab = (const char*)g_Xhi;  Bb = (const char*)g_Whi;
            sA = (size_t)DIN * 2;     kb = (size_t)c * 128;
        } else if (c < 96) {
            Ab = (const char*)g_Xlo8; Bb = (const char*)g_Whi8;
            sA = (size_t)DIN;         kb = (size_t)(c - 64) * 128;
        } else {
            Ab = (const char*)g_Xhi8; Bb = (const char*)g_Wlo8;
            sA = (size_t)DIN;         kb = (size_t)(c - 96) * 128;
        }
        const uint32_t aB = sbase + stage * STAGE_BYTES;
        const uint32_t bB = aB + 16384;
#pragma unroll
        for (int i = 0; i < 4; i++)
            cp_async16(aB + dstL[i], Ab + (size_t)(bm + rowL[i]) * sA + kb + colByte[i]);
#pragma unroll
        for (int i = 0; i < 4; i++)
            cp_async16(bB + dstL[i], Bb + (size_t)(bn + rowL[i]) * sA + kb + colByte[i]);
    };

    // prologue: 2 chunks in flight
    load_chunk(0, 0); CP_COMMIT();
    load_chunk(1, 1); CP_COMMIT();

    for (int c = 0; c < NCHUNK; c++) {
        if (c + 1 < NCHUNK) { CP_WAIT(1); } else { CP_WAIT(0); }
        __syncthreads();
        if (c + 2 < NCHUNK) { load_chunk(c + 2, (c + 2) % NSTAGE); CP_COMMIT(); }

        const uint32_t aB = sbase + (c % NSTAGE) * STAGE_BYTES;
        const uint32_t bB = aB + 16384;
        if (c < 64) {
#pragma unroll
            for (int ks = 0; ks < 4; ks++) {
                uint32_t a[2][4];
                ldsm_x4(a[0], aB + relA[0][ks]);
                ldsm_x4(a[1], aB + relA[1][ks]);
                uint32_t b[4][4];
#pragma unroll
                for (int p = 0; p < 4; p++) ldsm_x4(b[p], bB + relB[p][ks]);
#pragma unroll
                for (int mt = 0; mt < 2; mt++)
#pragma unroll
                    for (int nt = 0; nt < 8; nt++)
                        mma_bf16(acc[mt][nt], a[mt],
                                 b[nt >> 1][(nt & 1) * 2], b[nt >> 1][(nt & 1) * 2 + 1]);
            }
        } else {
#pragma unroll
            for (int ks = 0; ks < 4; ks++) {
                uint32_t a[2][4];
                ldsm_x4(a[0], aB + relA[0][ks]);
                ldsm_x4(a[1], aB + relA[1][ks]);
                uint32_t b[4][4];
#pragma unroll
                for (int p = 0; p < 4; p++) ldsm_x4(b[p], bB + relB[p][ks]);
#pragma unroll
                for (int mt = 0; mt < 2; mt++)
#pragma unroll
                    for (int nt = 0; nt < 8; nt++)
                        mma_fp8(acc[mt][nt], a[mt],
                                b[nt >> 1][(nt & 1) * 2], b[nt >> 1][(nt & 1) * 2 + 1]);
            }
        }
    }

    // epilogue: add bias, float2 stores
    const int group = lane >> 2;
    const int tig   = lane & 3;
#pragma unroll
    for (int nt = 0; nt < 8; nt++) {
        const int col = bn + warpN * 64 + nt * 8 + tig * 2;
        const float2 bv = *(const float2*)(bias + col);
#pragma unroll
        for (int mt = 0; mt < 2; mt++) {
            const int row0 = bm + warpM * 32 + mt * 16 + group;
            float* p0 = out + (size_t)row0 * DOUT + col;
            float* p1 = out + (size_t)(row0 + 8) * DOUT + col;
            *(float2*)p0 = make_float2(acc[mt][nt][0] + bv.x, acc[mt][nt][1] + bv.y);
            *(float2*)p1 = make_float2(acc[mt][nt][2] + bv.x, acc[mt][nt][3] + bv.y);
        }
    }
}

// ---------------------------------------------------------------------------
// Launch
// ---------------------------------------------------------------------------
extern "C" void kernel_launch(void* const* d_in, const int* in_sizes, int n_in,
                              void* d_out, int out_size) {
    const float* x      = (const float*)d_in[0];
    const float* W      = (const float*)d_in[1];
    const float* b      = (const float*)d_in[2];
    const float* lora_A = (const float*)d_in[3];
    const float* lora_B = (const float*)d_in[4];
    const float* delta  = (const float*)d_in[5];
    const void*  mask   = d_in[6];

    static bool attr_done = false;
    if (!attr_done) {
        cudaFuncSetAttribute(gemm_kernel,
                             cudaFuncAttributeMaxDynamicSharedMemorySize, SMEM_TOTAL);
        attr_done = true;
    }

    reset_flags_kernel<<<1, 1>>>();
    detect_mask_kernel<<<256, 256>>>((const unsigned int*)mask, 4 * 1024 * 1024);
    resolve_mode_kernel<<<1, 1>>>();

    fold_kernel<<<DOUT, 256>>>(W, lora_A, lora_B, delta, mask);
    convert_x_kernel<<<(MTOT * DIN) / 4 / 256, 256>>>(x);

    dim3 grid(MTOT / BM, DOUT / BN);   // (64, 32), m fastest
    gemm_kernel<<<grid, 256, SMEM_TOTAL>>>(b, (float*)d_out);
}

// round 7
// speedup vs baseline: 3.1843x; 3.1843x over previous
#include <cuda_runtime.h>
#include <cuda_fp16.h>
#include <cstdint>

// ---------------------------------------------------------------------------
// Problem constants
// ---------------------------------------------------------------------------
#define DIN   4096
#define DOUT  4096
#define MTOT  8192
#define BK    64                          // fp16 k-elems per chunk (128 B/row)
#define NCHUNK (DIN / BK)                 // 64 — single fp16 pass
#define BM    128
#define BN    128
#define NSTAGE 3
#define STAGE_BYTES 32768                 // A 16KB + B 16KB
#define SMEM_TOTAL (NSTAGE * STAGE_BYTES) // 96 KB
static __device__ __constant__ float kScaling = 2.0f;   // 32 / rank(16)

// ---------------------------------------------------------------------------
// Device-global scratch
// ---------------------------------------------------------------------------
__device__ __half g_Xh[(size_t)MTOT * DIN];   // fp16(x)
__device__ __half g_Wh[(size_t)DOUT * DIN];   // fp16(W_eff)
__device__ int g_flags[2];
__device__ int g_mode;

// ---------------------------------------------------------------------------
// Helpers (baseline PTX only — compiles at compute_103)
// ---------------------------------------------------------------------------
__device__ __forceinline__ uint32_t smem_u32(const void* p) {
    uint32_t a;
    asm("{ .reg .u64 t; cvta.to.shared.u64 t, %1; cvt.u32.u64 %0, t; }" : "=r"(a) : "l"(p));
    return a;
}
__device__ __forceinline__ void cp_async16(uint32_t dst, const void* src) {
    asm volatile("cp.async.cg.shared.global [%0], [%1], 16;"
                 :: "r"(dst), "l"(__cvta_generic_to_global(src)));
}
#define CP_COMMIT() asm volatile("cp.async.commit_group;" ::: "memory")
#define CP_WAIT(n)  asm volatile("cp.async.wait_group %0;" :: "n"(n) : "memory")

__device__ __forceinline__ uint32_t swz(uint32_t o) { return o ^ ((o >> 3) & 0x70); }

__device__ __forceinline__ void ldsm_x4(uint32_t* r, uint32_t addr) {
    asm volatile("ldmatrix.sync.aligned.m8n8.x4.shared.b16 {%0,%1,%2,%3}, [%4];"
                 : "=r"(r[0]), "=r"(r[1]), "=r"(r[2]), "=r"(r[3]) : "r"(addr));
}
__device__ __forceinline__ void mma_fp16(float* c, const uint32_t* a,
                                         uint32_t b0, uint32_t b1) {
    asm volatile(
        "mma.sync.aligned.m16n8k16.row.col.f32.f16.f16.f32 "
        "{%0,%1,%2,%3}, {%4,%5,%6,%7}, {%8,%9}, {%0,%1,%2,%3};"
        : "+f"(c[0]), "+f"(c[1]), "+f"(c[2]), "+f"(c[3])
        : "r"(a[0]), "r"(a[1]), "r"(a[2]), "r"(a[3]), "r"(b0), "r"(b1));
}

// ---------------------------------------------------------------------------
// Mask dtype detection (first 16MB scan = safe lower bound for all dtypes)
// ---------------------------------------------------------------------------
__global__ void reset_flags_kernel() { g_flags[0] = 0; g_flags[1] = 0; }

__global__ void detect_mask_kernel(const unsigned int* __restrict__ w, int nwords) {
    int notF = 0, notI = 0;
    int stride = gridDim.x * blockDim.x;
    for (int i = blockIdx.x * blockDim.x + threadIdx.x; i < nwords; i += stride) {
        unsigned int v = w[i];
        if (v != 0u && v != 0x3F800000u) notF = 1;
        if (v > 1u)                       notI = 1;
    }
    notF = __any_sync(0xFFFFFFFFu, notF);
    notI = __any_sync(0xFFFFFFFFu, notI);
    if ((threadIdx.x & 31) == 0) {
        if (notF) atomicOr(&g_flags[0], 1);
        if (notI) atomicOr(&g_flags[1], 1);
    }
}
__global__ void resolve_mode_kernel() {
    g_mode = (g_flags[0] == 0) ? 0 : ((g_flags[1] == 0) ? 1 : 2);
}

// ---------------------------------------------------------------------------
// Fold W_eff = W + delta*mask + 2*(B@A) → fp16
// ---------------------------------------------------------------------------
__global__ void fold_kernel(const float* __restrict__ W,
                            const float* __restrict__ lora_A,
                            const float* __restrict__ lora_B,
                            const float* __restrict__ delta,
                            const void*  __restrict__ maskp) {
    int o = blockIdx.x;
    __shared__ float br[16];
    if (threadIdx.x < 16) br[threadIdx.x] = lora_B[o * 16 + threadIdx.x] * kScaling;
    __syncthreads();

    const int mode = g_mode;
    const size_t rowoff = (size_t)o * DIN;

    for (int d = threadIdx.x * 4; d < DIN; d += blockDim.x * 4) {
        float4 w4 = *(const float4*)(W + rowoff + d);
        float4 dl = *(const float4*)(delta + rowoff + d);

        float m0, m1, m2, m3;
        if (mode == 0) {
            float4 mf = *(const float4*)((const float*)maskp + rowoff + d);
            m0 = mf.x; m1 = mf.y; m2 = mf.z; m3 = mf.w;
        } else if (mode == 1) {
            int4 mi = *(const int4*)((const int*)maskp + rowoff + d);
            m0 = mi.x ? 1.f : 0.f; m1 = mi.y ? 1.f : 0.f;
            m2 = mi.z ? 1.f : 0.f; m3 = mi.w ? 1.f : 0.f;
        } else {
            uchar4 mu = *(const uchar4*)((const unsigned char*)maskp + rowoff + d);
            m0 = mu.x ? 1.f : 0.f; m1 = mu.y ? 1.f : 0.f;
            m2 = mu.z ? 1.f : 0.f; m3 = mu.w ? 1.f : 0.f;
        }

        float l0 = 0.f, l1 = 0.f, l2 = 0.f, l3 = 0.f;
#pragma unroll
        for (int r = 0; r < 16; r++) {
            float4 a4 = *(const float4*)(lora_A + (size_t)r * DIN + d);
            float s = br[r];
            l0 = fmaf(s, a4.x, l0); l1 = fmaf(s, a4.y, l1);
            l2 = fmaf(s, a4.z, l2); l3 = fmaf(s, a4.w, l3);
        }

        float v0 = w4.x + dl.x * m0 + l0;
        float v1 = w4.y + dl.y * m1 + l1;
        float v2 = w4.z + dl.z * m2 + l2;
        float v3 = w4.w + dl.w * m3 + l3;

        __half2 h01 = __floats2half2_rn(v0, v1);
        __half2 h23 = __floats2half2_rn(v2, v3);
        uint2 H;
        H.x = *(const uint32_t*)&h01;
        H.y = *(const uint32_t*)&h23;
        *(uint2*)((char*)g_Wh + (rowoff + d) * 2) = H;
    }
}

// ---------------------------------------------------------------------------
// X → fp16
// ---------------------------------------------------------------------------
__global__ void convert_x_kernel(const float* __restrict__ x) {
    size_t base = ((size_t)blockIdx.x * blockDim.x + threadIdx.x) * 8;
    float4 a = *(const float4*)(x + base);
    float4 b = *(const float4*)(x + base + 4);
    __half2 h0 = __floats2half2_rn(a.x, a.y);
    __half2 h1 = __floats2half2_rn(a.z, a.w);
    __half2 h2 = __floats2half2_rn(b.x, b.y);
    __half2 h3 = __floats2half2_rn(b.z, b.w);
    uint4 H;
    H.x = *(const uint32_t*)&h0; H.y = *(const uint32_t*)&h1;
    H.z = *(const uint32_t*)&h2; H.w = *(const uint32_t*)&h3;
    *(uint4*)((char*)g_Xh + base * 2) = H;
}

// ---------------------------------------------------------------------------
// fp16 HMMA GEMM: out[128x128 tile] = Xh[128,4096]·Wh[128,4096]^T + bias
// 8 warps (4m × 2n), warp tile 32x64, mma m16n8k16, 3-stage cp.async pipe.
// ---------------------------------------------------------------------------
__global__ __launch_bounds__(256, 2)
void gemm_kernel(const float* __restrict__ bias, float* __restrict__ out) {
    extern __shared__ __align__(1024) char smem[];
    const uint32_t sbase = smem_u32(smem);
    const int tid = threadIdx.x;
    const int lane = tid & 31;
    const int wid = tid >> 5;
    const int warpM = wid >> 1;           // 0..3
    const int warpN = wid & 1;            // 0..1
    const int bm = blockIdx.x * BM;       // m fastest → W stays L2-resident
    const int bn = blockIdx.y * BN;

    // loader mapping: 4 A-slots + 4 B-slots of 16B per thread per chunk
    int rowL[4];  uint32_t dstL[4];  int colL[4];
#pragma unroll
    for (int i = 0; i < 4; i++) {
        int slot = tid + 256 * i;         // 0..1023
        rowL[i] = slot >> 3;              // 0..127
        colL[i] = (slot & 7) * 8;         // fp16 col
        dstL[i] = swz((uint32_t)(rowL[i] * 128 + (slot & 7) * 16));
    }

    // ldmatrix per-lane swizzled offsets (full-offset swizzle — R4 lesson)
    const int arow  = (lane & 7) + ((lane >> 3) & 1) * 8;
    const int acol  = ((lane >> 4) & 1) * 16;           // byte
    const int brow  = (lane & 7) + ((lane >> 4) & 1) * 8;
    const int bcol  = ((lane >> 3) & 1) * 16;           // byte
    uint32_t relA[2][4], relB[4][4];
#pragma unroll
    for (int mt = 0; mt < 2; mt++)
#pragma unroll
        for (int ks = 0; ks < 4; ks++)
            relA[mt][ks] = swz((uint32_t)((warpM * 32 + mt * 16 + arow) * 128 + ks * 32 + acol));
#pragma unroll
    for (int p = 0; p < 4; p++)
#pragma unroll
        for (int ks = 0; ks < 4; ks++)
            relB[p][ks] = swz((uint32_t)((warpN * 64 + p * 16 + brow) * 128 + ks * 32 + bcol));

    float acc[2][8][4];
#pragma unroll
    for (int mt = 0; mt < 2; mt++)
#pragma unroll
        for (int nt = 0; nt < 8; nt++)
#pragma unroll
            for (int q = 0; q < 4; q++) acc[mt][nt][q] = 0.f;

    auto load_chunk = [&](int c, int stage) {
        const int kk = c << 6;
        const uint32_t aB = sbase + stage * STAGE_BYTES;
        const uint32_t bB = aB + 16384;
#pragma unroll
        for (int i = 0; i < 4; i++)
            cp_async16(aB + dstL[i], g_Xh + (size_t)(bm + rowL[i]) * DIN + kk + colL[i]);
#pragma unroll
        for (int i = 0; i < 4; i++)
            cp_async16(bB + dstL[i], g_Wh + (size_t)(bn + rowL[i]) * DIN + kk + colL[i]);
    };

    // prologue: 2 chunks in flight
    load_chunk(0, 0); CP_COMMIT();
    load_chunk(1, 1); CP_COMMIT();

    for (int c = 0; c < NCHUNK; c++) {
        if (c + 1 < NCHUNK) { CP_WAIT(1); } else { CP_WAIT(0); }
        __syncthreads();
        if (c + 2 < NCHUNK) { load_chunk(c + 2, (c + 2) % NSTAGE); CP_COMMIT(); }

        const uint32_t aB = sbase + (c % NSTAGE) * STAGE_BYTES;
        const uint32_t bB = aB + 16384;
#pragma unroll
        for (int ks = 0; ks < 4; ks++) {
            uint32_t a[2][4];
            ldsm_x4(a[0], aB + relA[0][ks]);
            ldsm_x4(a[1], aB + relA[1][ks]);
            uint32_t b[4][4];
#pragma unroll
            for (int p = 0; p < 4; p++) ldsm_x4(b[p], bB + relB[p][ks]);
#pragma unroll
            for (int mt = 0; mt < 2; mt++)
#pragma unroll
                for (int nt = 0; nt < 8; nt++)
                    mma_fp16(acc[mt][nt], a[mt],
                             b[nt >> 1][(nt & 1) * 2], b[nt >> 1][(nt & 1) * 2 + 1]);
        }
    }

    // epilogue: add bias, float2 stores
    const int group = lane >> 2;
    const int tig   = lane & 3;
#pragma unroll
    for (int nt = 0; nt < 8; nt++) {
        const int col = bn + warpN * 64 + nt * 8 + tig * 2;
        const float2 bv = *(const float2*)(bias + col);
#pragma unroll
        for (int mt = 0; mt < 2; mt++) {
            const int row0 = bm + warpM * 32 + mt * 16 + group;
            float* p0 = out + (size_t)row0 * DOUT + col;
            float* p1 = out + (size_t)(row0 + 8) * DOUT + col;
            *(float2*)p0 = make_float2(acc[mt][nt][0] + bv.x, acc[mt][nt][1] + bv.y);
            *(float2*)p1 = make_float2(acc[mt][nt][2] + bv.x, acc[mt][nt][3] + bv.y);
        }
    }
}

// ---------------------------------------------------------------------------
// Launch
// ---------------------------------------------------------------------------
extern "C" void kernel_launch(void* const* d_in, const int* in_sizes, int n_in,
                              void* d_out, int out_size) {
    const float* x      = (const float*)d_in[0];
    const float* W      = (const float*)d_in[1];
    const float* b      = (const float*)d_in[2];
    const float* lora_A = (const float*)d_in[3];
    const float* lora_B = (const float*)d_in[4];
    const float* delta  = (const float*)d_in[5];
    const void*  mask   = d_in[6];

    static bool attr_done = false;
    if (!attr_done) {
        cudaFuncSetAttribute(gemm_kernel,
                             cudaFuncAttributeMaxDynamicSharedMemorySize, SMEM_TOTAL);
        attr_done = true;
    }

    reset_flags_kernel<<<1, 1>>>();
    detect_mask_kernel<<<256, 256>>>((const unsigned int*)mask, 4 * 1024 * 1024);
    resolve_mode_kernel<<<1, 1>>>();

    fold_kernel<<<DOUT, 256>>>(W, lora_A, lora_B, delta, mask);
    convert_x_kernel<<<(MTOT * DIN) / 8 / 256, 256>>>(x);

    dim3 grid(MTOT / BM, DOUT / BN);   // (64, 32), m fastest
    gemm_kernel<<<grid, 256, SMEM_TOTAL>>>(b, (float*)d_out);
}

// round 8
// speedup vs baseline: 3.2187x; 1.0108x over previous
#include <cuda_runtime.h>
#include <cuda_fp16.h>
#include <cstdint>

// ---------------------------------------------------------------------------
// Problem constants
// ---------------------------------------------------------------------------
#define DIN   4096
#define DOUT  4096
#define MTOT  8192
#define BK    64                          // fp16 k-elems per chunk (128 B/row)
#define NCHUNK (DIN / BK)                 // 64 — single fp16 pass
#define BM    128
#define BN    128
#define NSTAGE 3
#define STAGE_BYTES 32768                 // A 16KB + B 16KB
#define SMEM_TOTAL (NSTAGE * STAGE_BYTES) // 96 KB
static __device__ __constant__ float kScaling = 2.0f;   // 32 / rank(16)

// ---------------------------------------------------------------------------
// Device-global scratch
// ---------------------------------------------------------------------------
__device__ __half g_Xh[(size_t)MTOT * DIN];   // fp16(x)
__device__ __half g_Wh[(size_t)DOUT * DIN];   // fp16(W_eff)
__device__ int g_flags[2];
__device__ int g_mode;

// ---------------------------------------------------------------------------
// Helpers (baseline PTX only — compiles at compute_103)
// ---------------------------------------------------------------------------
__device__ __forceinline__ uint32_t smem_u32(const void* p) {
    uint32_t a;
    asm("{ .reg .u64 t; cvta.to.shared.u64 t, %1; cvt.u32.u64 %0, t; }" : "=r"(a) : "l"(p));
    return a;
}
__device__ __forceinline__ void cp_async16(uint32_t dst, const void* src) {
    asm volatile("cp.async.cg.shared.global [%0], [%1], 16;"
                 :: "r"(dst), "l"(__cvta_generic_to_global(src)));
}
#define CP_COMMIT() asm volatile("cp.async.commit_group;" ::: "memory")
#define CP_WAIT(n)  asm volatile("cp.async.wait_group %0;" :: "n"(n) : "memory")

__device__ __forceinline__ uint32_t swz(uint32_t o) { return o ^ ((o >> 3) & 0x70); }

__device__ __forceinline__ void ldsm_x4(uint32_t* r, uint32_t addr) {
    asm volatile("ldmatrix.sync.aligned.m8n8.x4.shared.b16 {%0,%1,%2,%3}, [%4];"
                 : "=r"(r[0]), "=r"(r[1]), "=r"(r[2]), "=r"(r[3]) : "r"(addr));
}
__device__ __forceinline__ void mma_fp16(float* c, const uint32_t* a,
                                         uint32_t b0, uint32_t b1) {
    asm volatile(
        "mma.sync.aligned.m16n8k16.row.col.f32.f16.f16.f32 "
        "{%0,%1,%2,%3}, {%4,%5,%6,%7}, {%8,%9}, {%0,%1,%2,%3};"
        : "+f"(c[0]), "+f"(c[1]), "+f"(c[2]), "+f"(c[3])
        : "r"(a[0]), "r"(a[1]), "r"(a[2]), "r"(a[3]), "r"(b0), "r"(b1));
}

// ---------------------------------------------------------------------------
// Mask dtype detection (first 16MB scan = safe lower bound for all dtypes)
// ---------------------------------------------------------------------------
__global__ void reset_flags_kernel() { g_flags[0] = 0; g_flags[1] = 0; }

__global__ void detect_mask_kernel(const unsigned int* __restrict__ w, int nwords) {
    int notF = 0, notI = 0;
    int stride = gridDim.x * blockDim.x;
    for (int i = blockIdx.x * blockDim.x + threadIdx.x; i < nwords; i += stride) {
        unsigned int v = w[i];
        if (v != 0u && v != 0x3F800000u) notF = 1;
        if (v > 1u)                       notI = 1;
    }
    notF = __any_sync(0xFFFFFFFFu, notF);
    notI = __any_sync(0xFFFFFFFFu, notI);
    if ((threadIdx.x & 31) == 0) {
        if (notF) atomicOr(&g_flags[0], 1);
        if (notI) atomicOr(&g_flags[1], 1);
    }
}
__global__ void resolve_mode_kernel() {
    g_mode = (g_flags[0] == 0) ? 0 : ((g_flags[1] == 0) ? 1 : 2);
}

// ---------------------------------------------------------------------------
// Fused prologue:
//   blocks [0, 4096)     : fold row o — W_eff = W + delta*mask + 2*(B@A) → fp16
//   blocks [4096, 8192)  : convert 2 rows of X → fp16
// Streaming convert blocks overlap the FFMA-latency-limited fold blocks.
// ---------------------------------------------------------------------------
__global__ void prep_kernel(const float* __restrict__ W,
                            const float* __restrict__ lora_A,
                            const float* __restrict__ lora_B,
                            const float* __restrict__ delta,
                            const void*  __restrict__ maskp,
                            const float* __restrict__ x) {
    if (blockIdx.x < DOUT) {
        // ---------------- fold one W row ----------------
        const int o = blockIdx.x;
        __shared__ float br[16];
        if (threadIdx.x < 16) br[threadIdx.x] = lora_B[o * 16 + threadIdx.x] * kScaling;
        __syncthreads();

        const int mode = g_mode;
        const size_t rowoff = (size_t)o * DIN;

        for (int d = threadIdx.x * 4; d < DIN; d += blockDim.x * 4) {
            float4 w4 = *(const float4*)(W + rowoff + d);
            float4 dl = *(const float4*)(delta + rowoff + d);

            float m0, m1, m2, m3;
            if (mode == 0) {
                float4 mf = *(const float4*)((const float*)maskp + rowoff + d);
                m0 = mf.x; m1 = mf.y; m2 = mf.z; m3 = mf.w;
            } else if (mode == 1) {
                int4 mi = *(const int4*)((const int*)maskp + rowoff + d);
                m0 = mi.x ? 1.f : 0.f; m1 = mi.y ? 1.f : 0.f;
                m2 = mi.z ? 1.f : 0.f; m3 = mi.w ? 1.f : 0.f;
            } else {
                uchar4 mu = *(const uchar4*)((const unsigned char*)maskp + rowoff + d);
                m0 = mu.x ? 1.f : 0.f; m1 = mu.y ? 1.f : 0.f;
                m2 = mu.z ? 1.f : 0.f; m3 = mu.w ? 1.f : 0.f;
            }

            float l0 = 0.f, l1 = 0.f, l2 = 0.f, l3 = 0.f;
#pragma unroll
            for (int r = 0; r < 16; r++) {
                float4 a4 = *(const float4*)(lora_A + (size_t)r * DIN + d);
                float s = br[r];
                l0 = fmaf(s, a4.x, l0); l1 = fmaf(s, a4.y, l1);
                l2 = fmaf(s, a4.z, l2); l3 = fmaf(s, a4.w, l3);
            }

            float v0 = w4.x + dl.x * m0 + l0;
            float v1 = w4.y + dl.y * m1 + l1;
            float v2 = w4.z + dl.z * m2 + l2;
            float v3 = w4.w + dl.w * m3 + l3;

            __half2 h01 = __floats2half2_rn(v0, v1);
            __half2 h23 = __floats2half2_rn(v2, v3);
            uint2 H;
            H.x = *(const uint32_t*)&h01;
            H.y = *(const uint32_t*)&h23;
            *(uint2*)((char*)g_Wh + (rowoff + d) * 2) = H;
        }
    } else {
        // ---------------- convert 2 rows of X ----------------
        const size_t rowbase = (size_t)(blockIdx.x - DOUT) * 2 * DIN;
#pragma unroll
        for (int it = 0; it < 4; it++) {
            size_t base = rowbase + ((size_t)it * blockDim.x + threadIdx.x) * 8;
            float4 a = *(const float4*)(x + base);
            float4 b = *(const float4*)(x + base + 4);
            __half2 h0 = __floats2half2_rn(a.x, a.y);
            __half2 h1 = __floats2half2_rn(a.z, a.w);
            __half2 h2 = __floats2half2_rn(b.x, b.y);
            __half2 h3 = __floats2half2_rn(b.z, b.w);
            uint4 H;
            H.x = *(const uint32_t*)&h0; H.y = *(const uint32_t*)&h1;
            H.z = *(const uint32_t*)&h2; H.w = *(const uint32_t*)&h3;
            *(uint4*)((char*)g_Xh + base * 2) = H;
        }
    }
}

// ---------------------------------------------------------------------------
// fp16 HMMA GEMM: out[128x128 tile] = Xh[128,4096]·Wh[128,4096]^T + bias
// 8 warps (4m × 2n), warp tile 32x64, mma m16n8k16, 3-stage cp.async pipe.
// ---------------------------------------------------------------------------
__global__ __launch_bounds__(256, 2)
void gemm_kernel(const float* __restrict__ bias, float* __restrict__ out) {
    extern __shared__ __align__(1024) char smem[];
    const uint32_t sbase = smem_u32(smem);
    const int tid = threadIdx.x;
    const int lane = tid & 31;
    const int wid = tid >> 5;
    const int warpM = wid >> 1;           // 0..3
    const int warpN = wid & 1;            // 0..1
    const int bm = blockIdx.x * BM;       // m fastest → W stays L2-resident
    const int bn = blockIdx.y * BN;

    // loader mapping: 4 A-slots + 4 B-slots of 16B per thread per chunk
    int rowL[4];  uint32_t dstL[4];  int colL[4];
#pragma unroll
    for (int i = 0; i < 4; i++) {
        int slot = tid + 256 * i;         // 0..1023
        rowL[i] = slot >> 3;              // 0..127
        colL[i] = (slot & 7) * 8;         // fp16 col
        dstL[i] = swz((uint32_t)(rowL[i] * 128 + (slot & 7) * 16));
    }

    // ldmatrix per-lane swizzled offsets (full-offset swizzle — R4 lesson)
    const int arow  = (lane & 7) + ((lane >> 3) & 1) * 8;
    const int acol  = ((lane >> 4) & 1) * 16;           // byte
    const int brow  = (lane & 7) + ((lane >> 4) & 1) * 8;
    const int bcol  = ((lane >> 3) & 1) * 16;           // byte
    uint32_t relA[2][4], relB[4][4];
#pragma unroll
    for (int mt = 0; mt < 2; mt++)
#pragma unroll
        for (int ks = 0; ks < 4; ks++)
            relA[mt][ks] = swz((uint32_t)((warpM * 32 + mt * 16 + arow) * 128 + ks * 32 + acol));
#pragma unroll
    for (int p = 0; p < 4; p++)
#pragma unroll
        for (int ks = 0; ks < 4; ks++)
            relB[p][ks] = swz((uint32_t)((warpN * 64 + p * 16 + brow) * 128 + ks * 32 + bcol));

    float acc[2][8][4];
#pragma unroll
    for (int mt = 0; mt < 2; mt++)
#pragma unroll
        for (int nt = 0; nt < 8; nt++)
#pragma unroll
            for (int q = 0; q < 4; q++) acc[mt][nt][q] = 0.f;

    auto load_chunk = [&](int c, int stage) {
        const int kk = c << 6;
        const uint32_t aB = sbase + stage * STAGE_BYTES;
        const uint32_t bB = aB + 16384;
#pragma unroll
        for (int i = 0; i < 4; i++)
            cp_async16(aB + dstL[i], g_Xh + (size_t)(bm + rowL[i]) * DIN + kk + colL[i]);
#pragma unroll
        for (int i = 0; i < 4; i++)
            cp_async16(bB + dstL[i], g_Wh + (size_t)(bn + rowL[i]) * DIN + kk + colL[i]);
    };

    // prologue: 2 chunks in flight
    load_chunk(0, 0); CP_COMMIT();
    load_chunk(1, 1); CP_COMMIT();

    for (int c = 0; c < NCHUNK; c++) {
        if (c + 1 < NCHUNK) { CP_WAIT(1); } else { CP_WAIT(0); }
        __syncthreads();
        if (c + 2 < NCHUNK) { load_chunk(c + 2, (c + 2) % NSTAGE); CP_COMMIT(); }

        const uint32_t aB = sbase + (c % NSTAGE) * STAGE_BYTES;
        const uint32_t bB = aB + 16384;
#pragma unroll
        for (int ks = 0; ks < 4; ks++) {
            uint32_t a[2][4];
            ldsm_x4(a[0], aB + relA[0][ks]);
            ldsm_x4(a[1], aB + relA[1][ks]);
            uint32_t b[4][4];
#pragma unroll
            for (int p = 0; p < 4; p++) ldsm_x4(b[p], bB + relB[p][ks]);
#pragma unroll
            for (int mt = 0; mt < 2; mt++)
#pragma unroll
                for (int nt = 0; nt < 8; nt++)
                    mma_fp16(acc[mt][nt], a[mt],
                             b[nt >> 1][(nt & 1) * 2], b[nt >> 1][(nt & 1) * 2 + 1]);
        }
    }

    // epilogue: add bias, float2 stores
    const int group = lane >> 2;
    const int tig   = lane & 3;
#pragma unroll
    for (int nt = 0; nt < 8; nt++) {
        const int col = bn + warpN * 64 + nt * 8 + tig * 2;
        const float2 bv = *(const float2*)(bias + col);
#pragma unroll
        for (int mt = 0; mt < 2; mt++) {
            const int row0 = bm + warpM * 32 + mt * 16 + group;
            float* p0 = out + (size_t)row0 * DOUT + col;
            float* p1 = out + (size_t)(row0 + 8) * DOUT + col;
            *(float2*)p0 = make_float2(acc[mt][nt][0] + bv.x, acc[mt][nt][1] + bv.y);
            *(float2*)p1 = make_float2(acc[mt][nt][2] + bv.x, acc[mt][nt][3] + bv.y);
        }
    }
}

// ---------------------------------------------------------------------------
// Launch
// ---------------------------------------------------------------------------
extern "C" void kernel_launch(void* const* d_in, const int* in_sizes, int n_in,
                              void* d_out, int out_size) {
    const float* x      = (const float*)d_in[0];
    const float* W      = (const float*)d_in[1];
    const float* b      = (const float*)d_in[2];
    const float* lora_A = (const float*)d_in[3];
    const float* lora_B = (const float*)d_in[4];
    const float* delta  = (const float*)d_in[5];
    const void*  mask   = d_in[6];

    static bool attr_done = false;
    if (!attr_done) {
        cudaFuncSetAttribute(gemm_kernel,
                             cudaFuncAttributeMaxDynamicSharedMemorySize, SMEM_TOTAL);
        attr_done = true;
    }

    reset_flags_kernel<<<1, 1>>>();
    detect_mask_kernel<<<256, 256>>>((const unsigned int*)mask, 4 * 1024 * 1024);
    resolve_mode_kernel<<<1, 1>>>();

    // fused fold (4096 blocks) + X convert (4096 blocks)
    prep_kernel<<<DOUT + MTOT / 2, 256>>>(W, lora_A, lora_B, delta, mask, x);

    dim3 grid(MTOT / BM, DOUT / BN);   // (64, 32), m fastest
    gemm_kernel<<<grid, 256, SMEM_TOTAL>>>(b, (float*)d_out);
}